// round 15
// baseline (speedup 1.0000x reference)
#include <cuda_runtime.h>
#include <cuda_fp16.h>
#include <math.h>
#include <stdint.h>

#define N_NODES 25000
#define N_EDGES 400000
#define D_NODE 512
#define D_EDGE 512
#define D_IN   1024
#define D_HID  512
#define D_OUT  512
#define LN_EPS 1e-5f
#define SCAN_NB 25        // ceil(25000/1024)
#define NODE_SPLIT 12544  // 98 exact 128-row GEMM tiles in half0
#define ECOPY 81920       // edge rows [0,ECOPY) copied by s2 during main's MLP tail

// ---------------- scratch (device globals; no cudaMalloc allowed) ----------
__device__ int    g_count[N_NODES];
__device__ int    g_off[N_NODES + 1];
__device__ int    g_cursor[N_NODES];
__device__ int    g_csr[N_EDGES];
__device__ int    g_blocksum[SCAN_NB];
__device__ int    g_blockbase[SCAN_NB];
__device__ __half g_cat[(size_t)N_NODES * D_IN];   // [agg | nfeat], fp16
__device__ __half g_h[(size_t)N_NODES * D_HID];    // silu(cat@w1+b1), fp16
__device__ float  g_y[(size_t)N_NODES * D_OUT];    // h@w2+b2 (pre-LN), f32
__device__ __half g_w1t[(size_t)D_HID * D_IN];     // w1^T [512,1024], fp16
__device__ __half g_w2t[(size_t)D_OUT * D_HID];    // w2^T [512,512], fp16

// ---------------- small helpers ---------------------------------------------
__device__ __forceinline__ uint32_t smem_u32_of(const void* p) {
    uint32_t a;
    asm("{ .reg .u64 t; cvta.to.shared.u64 t, %1; cvt.u32.u64 %0, t; }"
        : "=r"(a) : "l"(p));
    return a;
}

__device__ __forceinline__ uint32_t h2_bits(__half2 h) {
    uint32_t u;
    __builtin_memcpy(&u, &h, 4);
    return u;
}

__device__ __forceinline__ void cp16(uint32_t dst, const void* src) {
    asm volatile("cp.async.cg.shared.global [%0], [%1], 16;" :: "r"(dst), "l"(src));
}

__device__ __forceinline__ void mma_fp16(float* c, const uint32_t* a, const uint32_t* b) {
    asm volatile(
        "mma.sync.aligned.m16n8k16.row.col.f32.f16.f16.f32 "
        "{%0,%1,%2,%3}, {%4,%5,%6,%7}, {%8,%9}, {%0,%1,%2,%3};"
        : "+f"(c[0]), "+f"(c[1]), "+f"(c[2]), "+f"(c[3])
        : "r"(a[0]), "r"(a[1]), "r"(a[2]), "r"(a[3]), "r"(b[0]), "r"(b[1]));
}

// ---------------- CSR build ------------------------------------------------
__global__ void zero_count_kernel() {
    int i = blockIdx.x * blockDim.x + threadIdx.x;
    if (i < N_NODES) g_count[i] = 0;
}

__global__ void hist_kernel(const int* __restrict__ dst_idx) {
    int e = blockIdx.x * blockDim.x + threadIdx.x;
    if (e < N_EDGES) atomicAdd(&g_count[dst_idx[e]], 1);
}

// 3-phase multi-block exclusive scan of g_count -> g_off / g_cursor
__global__ void scan1_kernel() {   // grid SCAN_NB, block 1024
    __shared__ int s[1024];
    int b = blockIdx.x, t = threadIdx.x;
    int idx = b * 1024 + t;
    int v = (idx < N_NODES) ? g_count[idx] : 0;
    s[t] = v;
    __syncthreads();
    for (int d = 1; d < 1024; d <<= 1) {
        int x = 0;
        if (t >= d) x = s[t - d];
        __syncthreads();
        if (t >= d) s[t] += x;
        __syncthreads();
    }
    if (idx < N_NODES) g_off[idx] = s[t] - v;  // exclusive within block
    if (t == 1023) g_blocksum[b] = s[1023];
}

__global__ void scan2_kernel() {   // 1 block, 32 threads
    int t = threadIdx.x;
    int orig = (t < SCAN_NB) ? g_blocksum[t] : 0;
    int v = orig;
#pragma unroll
    for (int d = 1; d < 32; d <<= 1) {
        int x = __shfl_up_sync(0xffffffffu, v, d);
        if (t >= d) v += x;
    }
    if (t < SCAN_NB) g_blockbase[t] = v - orig;   // exclusive
    if (t == SCAN_NB - 1) g_off[N_NODES] = v;     // total
}

__global__ void scan3_kernel() {   // grid SCAN_NB, block 1024
    int b = blockIdx.x, t = threadIdx.x;
    int idx = b * 1024 + t;
    if (idx < N_NODES) {
        int o = g_off[idx] + g_blockbase[b];
        g_off[idx] = o;
        g_cursor[idx] = o;
    }
}

__global__ void fill_kernel(const int* __restrict__ dst_idx) {
    int e = blockIdx.x * blockDim.x + threadIdx.x;
    if (e < N_EDGES) {
        int p = atomicAdd(&g_cursor[dst_idx[e]], 1);
        g_csr[p] = e;
    }
}

// ---------------- standalone streaming copy (side stream, MLP-tail window) --
__global__ void copy_kernel(const float4* __restrict__ src, float4* __restrict__ dst, int n4) {
    int idx = blockIdx.x * blockDim.x + threadIdx.x;
    int stride = gridDim.x * blockDim.x;
    for (int i = idx; i < n4; i += stride)
        __stcs(dst + i, __ldcs(src + i));
}

// ---------------- aggregate + concat (+ partial fused passthrough) ----------
// one CTA (128 threads) per node (node id = n0 + blockIdx.x).
// Passthrough write rides the gather read, but only for ed >= ECOPY
// (rows below ECOPY are copied by s2 during main's tensor-bound MLP tail).
template <bool PASS>
__global__ void agg_concat_kernel(const float* __restrict__ efeat,
                                  const float* __restrict__ nfeat,
                                  float* __restrict__ out_e, int n0) {
    int n = n0 + blockIdx.x;
    int c = threadIdx.x * 4;
    float4 acc = make_float4(0.f, 0.f, 0.f, 0.f);
    int s = g_off[n];
    int e = g_off[n + 1];
    int i = s;
    for (; i + 1 < e; i += 2) {
        int ed0 = g_csr[i];
        int ed1 = g_csr[i + 1];
        const float4 v0 = __ldcs((const float4*)(efeat + (size_t)ed0 * D_EDGE + c));
        const float4 v1 = __ldcs((const float4*)(efeat + (size_t)ed1 * D_EDGE + c));
        if (PASS) {
            if (ed0 >= ECOPY) __stcs((float4*)(out_e + (size_t)ed0 * D_EDGE + c), v0);
            if (ed1 >= ECOPY) __stcs((float4*)(out_e + (size_t)ed1 * D_EDGE + c), v1);
        }
        acc.x += v0.x; acc.y += v0.y; acc.z += v0.z; acc.w += v0.w;
        acc.x += v1.x; acc.y += v1.y; acc.z += v1.z; acc.w += v1.w;
    }
    if (i < e) {
        int ed = g_csr[i];
        const float4 v = __ldcs((const float4*)(efeat + (size_t)ed * D_EDGE + c));
        if (PASS && ed >= ECOPY) __stcs((float4*)(out_e + (size_t)ed * D_EDGE + c), v);
        acc.x += v.x; acc.y += v.y; acc.z += v.z; acc.w += v.w;
    }
    __half2 h0 = __floats2half2_rn(acc.x, acc.y);
    __half2 h1 = __floats2half2_rn(acc.z, acc.w);
    *(uint2*)(g_cat + (size_t)n * D_IN + c) = make_uint2(h2_bits(h0), h2_bits(h1));
    const float4 nf = *(const float4*)(nfeat + (size_t)n * D_NODE + c);
    __half2 h2 = __floats2half2_rn(nf.x, nf.y);
    __half2 h3 = __floats2half2_rn(nf.z, nf.w);
    *(uint2*)(g_cat + (size_t)n * D_IN + D_EDGE + c) = make_uint2(h2_bits(h2), h2_bits(h3));
}

// ---------------- weight transpose + fp16 convert ---------------------------
__global__ void transpose_half_kernel(const float* __restrict__ src,
                                      __half* __restrict__ dst, int K, int N) {
    __shared__ float t[32][33];
    int k0 = blockIdx.x * 32, n0 = blockIdx.y * 32;
    int x = threadIdx.x, y0 = threadIdx.y;  // block (32, 8)
#pragma unroll
    for (int d = 0; d < 4; d++) {
        int k = k0 + y0 + d * 8;
        t[y0 + d * 8][x] = src[(size_t)k * N + n0 + x];
    }
    __syncthreads();
#pragma unroll
    for (int d = 0; d < 4; d++) {
        int n = n0 + y0 + d * 8;
        dst[(size_t)n * K + k0 + x] = __float2half_rn(t[x][y0 + d * 8]);
    }
}

// ---------------- fp16 mma.sync GEMM over node range [M0, M_end) ------------
#define HS_STRIDE 40                          // halves per row
#define HS_TILE   (128 * HS_STRIDE * 2)       // bytes per tile: 10240
#define HS_STAGE  (2 * HS_TILE)               // 20480
#define HS_TOTAL  (2 * HS_STAGE)              // 40960

template <bool SILU, bool OUT_HALF>
__global__ void __launch_bounds__(256) mma_gemm_kernel(
    const __half* __restrict__ A, const __half* __restrict__ Bt,
    const float* __restrict__ bias, void* __restrict__ Cv,
    int M0, int M_end, int K)
{
    extern __shared__ char smem[];
    const __half* sh = (const __half*)smem;
    const uint32_t sb = smem_u32_of(smem);
    const int tid = threadIdx.x;
    const int lane = tid & 31;
    const int wid = tid >> 5;
    const int warpRow = wid >> 2;          // 0..1
    const int warpCol = wid & 3;           // 0..3
    const int rowBase = M0 + blockIdx.y * 128;
    const int colBase = blockIdx.x * 128;
    const int NC = K >> 5;

    auto load_chunk = [&](int c, int s) {
        const int kc0 = c << 5;
        const uint32_t stg = (uint32_t)(s * HS_STAGE);
#pragma unroll
        for (int i = 0; i < 2; i++) {
            int idx = tid + (i << 8);          // 0..511
            int r = idx >> 2, seg = idx & 3;
            int gr = rowBase + r;
            if (gr >= M_end) gr = M_end - 1;
            cp16(sb + stg + (uint32_t)(r * (HS_STRIDE * 2) + seg * 16),
                 A + (size_t)gr * K + kc0 + seg * 8);
        }
#pragma unroll
        for (int i = 0; i < 2; i++) {
            int idx = tid + (i << 8);
            int r = idx >> 2, seg = idx & 3;
            cp16(sb + stg + HS_TILE + (uint32_t)(r * (HS_STRIDE * 2) + seg * 16),
                 Bt + (size_t)(colBase + r) * K + kc0 + seg * 8);
        }
        asm volatile("cp.async.commit_group;" ::: "memory");
    };

    float acc[4][4][4];
#pragma unroll
    for (int i = 0; i < 4; i++)
#pragma unroll
        for (int j = 0; j < 4; j++)
#pragma unroll
            for (int r = 0; r < 4; r++) acc[i][j][r] = 0.f;

    load_chunk(0, 0);
    if (NC > 1) load_chunk(1, 1);

    for (int c = 0; c < NC; c++) {
        const int s = c & 1;
        if (c + 1 < NC) asm volatile("cp.async.wait_group 1;" ::: "memory");
        else            asm volatile("cp.async.wait_group 0;" ::: "memory");
        __syncthreads();

        const __half* As = sh + s * (HS_STAGE / 2);
        const __half* Bs = As + (HS_TILE / 2);

#pragma unroll
        for (int ks = 0; ks < 2; ks++) {
            const int kc = (ks << 4) + ((lane & 3) << 1);
            uint32_t af[4][4], bf[4][2];
#pragma unroll
            for (int t = 0; t < 4; t++) {
                int r0 = warpRow * 64 + t * 16 + (lane >> 2);
                af[t][0] = *(const uint32_t*)(As + r0 * HS_STRIDE + kc);
                af[t][1] = *(const uint32_t*)(As + (r0 + 8) * HS_STRIDE + kc);
                af[t][2] = *(const uint32_t*)(As + r0 * HS_STRIDE + kc + 8);
                af[t][3] = *(const uint32_t*)(As + (r0 + 8) * HS_STRIDE + kc + 8);
            }
#pragma unroll
            for (int t = 0; t < 4; t++) {
                int n0 = warpCol * 32 + t * 8 + (lane >> 2);
                bf[t][0] = *(const uint32_t*)(Bs + n0 * HS_STRIDE + kc);
                bf[t][1] = *(const uint32_t*)(Bs + n0 * HS_STRIDE + kc + 8);
            }
#pragma unroll
            for (int mt = 0; mt < 4; mt++)
#pragma unroll
                for (int nt = 0; nt < 4; nt++)
                    mma_fp16(acc[mt][nt], af[mt], bf[nt]);
        }
        __syncthreads();
        if (c + 2 < NC) load_chunk(c + 2, s);
    }

    // epilogue
#pragma unroll
    for (int mt = 0; mt < 4; mt++) {
        int r0 = rowBase + warpRow * 64 + mt * 16 + (lane >> 2);
#pragma unroll
        for (int nt = 0; nt < 4; nt++) {
            int gc = colBase + warpCol * 32 + nt * 8 + ((lane & 3) << 1);
            float bx = bias[gc], by = bias[gc + 1];
#pragma unroll
            for (int h = 0; h < 2; h++) {
                int gr = r0 + h * 8;
                if (gr >= M_end) continue;
                float vx = acc[mt][nt][h * 2 + 0] + bx;
                float vy = acc[mt][nt][h * 2 + 1] + by;
                if (SILU) {
                    vx = vx / (1.f + __expf(-vx));
                    vy = vy / (1.f + __expf(-vy));
                }
                if (OUT_HALF) {
                    __half2 hv = __floats2half2_rn(vx, vy);
                    *(uint32_t*)((__half*)Cv + (size_t)gr * 512 + gc) = h2_bits(hv);
                } else {
                    *(float2*)((float*)Cv + (size_t)gr * 512 + gc) = make_float2(vx, vy);
                }
            }
        }
    }
}

// ---------------- LayerNorm + residual (node id = n0 + blockIdx.x) ----------
__global__ void ln_residual_kernel(const float* __restrict__ nfeat,
                                   const float* __restrict__ gamma,
                                   const float* __restrict__ beta,
                                   float* __restrict__ out, int n0) {
    int n = n0 + blockIdx.x;
    int c = threadIdx.x * 4;
    const float4 v = *(const float4*)(g_y + (size_t)n * D_OUT + c);

    __shared__ float sm[4];
    __shared__ float sm2[4];
    int lane = threadIdx.x & 31;
    int w = threadIdx.x >> 5;

    float s = v.x + v.y + v.z + v.w;
#pragma unroll
    for (int o = 16; o > 0; o >>= 1) s += __shfl_xor_sync(0xffffffffu, s, o);
    if (lane == 0) sm[w] = s;
    __syncthreads();
    float mu = (sm[0] + sm[1] + sm[2] + sm[3]) * (1.f / 512.f);

    float dx = v.x - mu, dy = v.y - mu, dz = v.z - mu, dw = v.w - mu;
    float sq = dx * dx + dy * dy + dz * dz + dw * dw;
#pragma unroll
    for (int o = 16; o > 0; o >>= 1) sq += __shfl_xor_sync(0xffffffffu, sq, o);
    if (lane == 0) sm2[w] = sq;
    __syncthreads();
    float var = (sm2[0] + sm2[1] + sm2[2] + sm2[3]) * (1.f / 512.f);
    float inv = rsqrtf(var + LN_EPS);

    const float4 g = *(const float4*)(gamma + c);
    const float4 b = *(const float4*)(beta + c);
    const float4 nf = *(const float4*)(nfeat + (size_t)n * D_NODE + c);
    float4 o4;
    o4.x = dx * inv * g.x + b.x + nf.x;
    o4.y = dy * inv * g.y + b.y + nf.y;
    o4.z = dz * inv * g.z + b.z + nf.z;
    o4.w = dw * inv * g.w + b.w + nf.w;
    *(float4*)(out + (size_t)n * D_OUT + c) = o4;
}

// ---------------- launch ----------------------------------------------------
extern "C" void kernel_launch(void* const* d_in, const int* in_sizes, int n_in,
                              void* d_out, int out_size) {
    const float* efeat   = (const float*)d_in[0];
    const float* nfeat   = (const float*)d_in[1];
    const int*   dst_idx = (const int*)  d_in[2];
    const float* w1      = (const float*)d_in[3];
    const float* b1      = (const float*)d_in[4];
    const float* w2      = (const float*)d_in[5];
    const float* b2      = (const float*)d_in[6];
    const float* gamma   = (const float*)d_in[7];
    const float* beta    = (const float*)d_in[8];

    // device addresses of scratch symbols (NOT the host shadow — see R1)
    __half *cat_p = nullptr, *h_p = nullptr, *w1t_p = nullptr, *w2t_p = nullptr;
    float  *y_p = nullptr;
    cudaGetSymbolAddress((void**)&cat_p, g_cat);
    cudaGetSymbolAddress((void**)&h_p,   g_h);
    cudaGetSymbolAddress((void**)&y_p,   g_y);
    cudaGetSymbolAddress((void**)&w1t_p, g_w1t);
    cudaGetSymbolAddress((void**)&w2t_p, g_w2t);

    cudaFuncSetAttribute((const void*)mma_gemm_kernel<true, true>,
                         cudaFuncAttributeMaxDynamicSharedMemorySize, HS_TOTAL);
    cudaFuncSetAttribute((const void*)mma_gemm_kernel<false, false>,
                         cudaFuncAttributeMaxDynamicSharedMemorySize, HS_TOTAL);

    float* out = (float*)d_out;
    float* out_nodes;
    const long long full = (long long)N_EDGES * D_EDGE + (long long)N_NODES * D_OUT;
    const bool pass = ((long long)out_size >= full);
    out_nodes = pass ? out + (size_t)N_EDGES * D_EDGE : out;

    // side stream + fork/join events (no device memory alloc)
    cudaStream_t s2 = 0;
    cudaStreamCreateWithFlags(&s2, cudaStreamNonBlocking);
    cudaEvent_t evFork = 0, evW = 0, evA = 0, evB = 0;
    cudaEventCreateWithFlags(&evFork, cudaEventDisableTiming);
    cudaEventCreateWithFlags(&evW, cudaEventDisableTiming);
    cudaEventCreateWithFlags(&evA, cudaEventDisableTiming);
    cudaEventCreateWithFlags(&evB, cudaEventDisableTiming);

    // legal capture fork: s2's first op waits on an origin-stream event
    cudaEventRecord(evFork, 0);
    cudaStreamWaitEvent(s2, evFork, 0);

    // side stream: transposes only (weights ready early)
    {
        dim3 b(32, 8);
        transpose_half_kernel<<<dim3(D_IN / 32, D_HID / 32), b, 0, s2>>>(w1, w1t_p, D_IN, D_HID);
        transpose_half_kernel<<<dim3(D_HID / 32, D_OUT / 32), b, 0, s2>>>(w2, w2t_p, D_HID, D_OUT);
        cudaEventRecord(evW, s2);
    }

    // CSR build (main)
    zero_count_kernel<<<(N_NODES + 255) / 256, 256>>>();
    hist_kernel<<<(N_EDGES + 255) / 256, 256>>>(dst_idx);
    scan1_kernel<<<SCAN_NB, 1024>>>();
    scan2_kernel<<<1, 32>>>();
    scan3_kernel<<<SCAN_NB, 1024>>>();
    fill_kernel<<<(N_EDGES + 255) / 256, 256>>>(dst_idx);

    const int S = NODE_SPLIT;                    // 12544 = 98 x 128
    const int tiles0 = S / 128;                  // 98
    const int tiles1 = (N_NODES - S + 127) / 128;// 98

    // main: agg half0 (lighter now: no stores for ed < ECOPY), then fork
    if (pass) agg_concat_kernel<true><<<S, 128>>>(efeat, nfeat, out, 0);
    else      agg_concat_kernel<false><<<S, 128>>>(efeat, nfeat, nullptr, 0);
    cudaEventRecord(evA, 0);

    // main: agg half1 (DRAM-bound) ...
    if (pass) agg_concat_kernel<true><<<N_NODES - S, 128>>>(efeat, nfeat, out, S);
    else      agg_concat_kernel<false><<<N_NODES - S, 128>>>(efeat, nfeat, nullptr, S);

    // ... while s2 runs the (tensor-bound) MLP+LN chain for half0, THEN the
    // ECOPY passthrough copy — which lands in main's half1-MLP window, where
    // DRAM is idle (GEMMs read only ~64MB). R13/R14 put it in the CSR window
    // where it collided with DRAM-bound agg; that regressed twice.
    cudaStreamWaitEvent(s2, evA, 0);
    mma_gemm_kernel<true, true><<<dim3(4, tiles0), 256, HS_TOTAL, s2>>>(
        cat_p, w1t_p, b1, h_p, 0, S, D_IN);
    mma_gemm_kernel<false, false><<<dim3(4, tiles0), 256, HS_TOTAL, s2>>>(
        h_p, w2t_p, b2, y_p, 0, S, D_HID);
    ln_residual_kernel<<<S, 128, 0, s2>>>(nfeat, gamma, beta, out_nodes, 0);
    if (pass) {
        int n4 = ECOPY * D_EDGE / 4;   // 10.49M float4
        copy_kernel<<<2048, 256, 0, s2>>>((const float4*)efeat, (float4*)out, n4);
    }
    cudaEventRecord(evB, s2);

    // main: needs weights here, before its own GEMM tail
    cudaStreamWaitEvent(0, evW, 0);
    mma_gemm_kernel<true, true><<<dim3(4, tiles1), 256, HS_TOTAL>>>(
        cat_p, w1t_p, b1, h_p, S, N_NODES, D_IN);
    mma_gemm_kernel<false, false><<<dim3(4, tiles1), 256, HS_TOTAL>>>(
        h_p, w2t_p, b2, y_p, S, N_NODES, D_HID);
    ln_residual_kernel<<<N_NODES - S, 128>>>(nfeat, gamma, beta, out_nodes, S);

    // join
    cudaStreamWaitEvent(0, evB, 0);
}

// round 16
// speedup vs baseline: 1.0502x; 1.0502x over previous
#include <cuda_runtime.h>
#include <cuda_fp16.h>
#include <math.h>
#include <stdint.h>

#define N_NODES 25000
#define N_EDGES 400000
#define D_NODE 512
#define D_EDGE 512
#define D_IN   1024
#define D_HID  512
#define D_OUT  512
#define LN_EPS 1e-5f
#define SCAN_NB 25        // ceil(25000/1024)
#define NODE_SPLIT 12544  // 98 exact 128-row GEMM tiles in half0

// ---------------- scratch (device globals; no cudaMalloc allowed) ----------
__device__ int    g_count[N_NODES];
__device__ int    g_off[N_NODES + 1];
__device__ int    g_cursor[N_NODES];
__device__ int    g_csr[N_EDGES];
__device__ int    g_blocksum[SCAN_NB];
__device__ int    g_blockbase[SCAN_NB];
__device__ __half g_cat[(size_t)N_NODES * D_IN];   // [agg | nfeat], fp16
__device__ __half g_h[(size_t)N_NODES * D_HID];    // silu(cat@w1+b1), fp16
__device__ __half g_y[(size_t)N_NODES * D_OUT];    // h@w2+b2 (pre-LN), fp16
__device__ __half g_w1t[(size_t)D_HID * D_IN];     // w1^T [512,1024], fp16
__device__ __half g_w2t[(size_t)D_OUT * D_HID];    // w2^T [512,512], fp16

// ---------------- small helpers ---------------------------------------------
__device__ __forceinline__ uint32_t smem_u32_of(const void* p) {
    uint32_t a;
    asm("{ .reg .u64 t; cvta.to.shared.u64 t, %1; cvt.u32.u64 %0, t; }"
        : "=r"(a) : "l"(p));
    return a;
}

__device__ __forceinline__ uint32_t h2_bits(__half2 h) {
    uint32_t u;
    __builtin_memcpy(&u, &h, 4);
    return u;
}

__device__ __forceinline__ void cp16(uint32_t dst, const void* src) {
    asm volatile("cp.async.cg.shared.global [%0], [%1], 16;" :: "r"(dst), "l"(src));
}

__device__ __forceinline__ void mma_fp16(float* c, const uint32_t* a, const uint32_t* b) {
    asm volatile(
        "mma.sync.aligned.m16n8k16.row.col.f32.f16.f16.f32 "
        "{%0,%1,%2,%3}, {%4,%5,%6,%7}, {%8,%9}, {%0,%1,%2,%3};"
        : "+f"(c[0]), "+f"(c[1]), "+f"(c[2]), "+f"(c[3])
        : "r"(a[0]), "r"(a[1]), "r"(a[2]), "r"(a[3]), "r"(b[0]), "r"(b[1]));
}

// ---------------- CSR build ------------------------------------------------
__global__ void zero_count_kernel() {
    int i = blockIdx.x * blockDim.x + threadIdx.x;
    if (i < N_NODES) g_count[i] = 0;
}

__global__ void hist_kernel(const int* __restrict__ dst_idx) {
    int e = blockIdx.x * blockDim.x + threadIdx.x;
    if (e < N_EDGES) atomicAdd(&g_count[dst_idx[e]], 1);
}

// 3-phase multi-block exclusive scan of g_count -> g_off / g_cursor
__global__ void scan1_kernel() {   // grid SCAN_NB, block 1024
    __shared__ int s[1024];
    int b = blockIdx.x, t = threadIdx.x;
    int idx = b * 1024 + t;
    int v = (idx < N_NODES) ? g_count[idx] : 0;
    s[t] = v;
    __syncthreads();
    for (int d = 1; d < 1024; d <<= 1) {
        int x = 0;
        if (t >= d) x = s[t - d];
        __syncthreads();
        if (t >= d) s[t] += x;
        __syncthreads();
    }
    if (idx < N_NODES) g_off[idx] = s[t] - v;  // exclusive within block
    if (t == 1023) g_blocksum[b] = s[1023];
}

__global__ void scan2_kernel() {   // 1 block, 32 threads
    int t = threadIdx.x;
    int orig = (t < SCAN_NB) ? g_blocksum[t] : 0;
    int v = orig;
#pragma unroll
    for (int d = 1; d < 32; d <<= 1) {
        int x = __shfl_up_sync(0xffffffffu, v, d);
        if (t >= d) v += x;
    }
    if (t < SCAN_NB) g_blockbase[t] = v - orig;   // exclusive
    if (t == SCAN_NB - 1) g_off[N_NODES] = v;     // total
}

__global__ void scan3_kernel() {   // grid SCAN_NB, block 1024
    int b = blockIdx.x, t = threadIdx.x;
    int idx = b * 1024 + t;
    if (idx < N_NODES) {
        int o = g_off[idx] + g_blockbase[b];
        g_off[idx] = o;
        g_cursor[idx] = o;
    }
}

__global__ void fill_kernel(const int* __restrict__ dst_idx) {
    int e = blockIdx.x * blockDim.x + threadIdx.x;
    if (e < N_EDGES) {
        int p = atomicAdd(&g_cursor[dst_idx[e]], 1);
        g_csr[p] = e;
    }
}

// ---------------- aggregate + concat (+ FULLY fused efeat passthrough) ------
// one CTA (128 threads) per node (node id = n0 + blockIdx.x).
// Every edge row appears exactly once in the CSR; the passthrough write rides
// the gather read. (Standalone-copy variants re-read efeat and regressed 3x.)
template <bool PASS>
__global__ void agg_concat_kernel(const float* __restrict__ efeat,
                                  const float* __restrict__ nfeat,
                                  float* __restrict__ out_e, int n0) {
    int n = n0 + blockIdx.x;
    int c = threadIdx.x * 4;
    float4 acc = make_float4(0.f, 0.f, 0.f, 0.f);
    int s = g_off[n];
    int e = g_off[n + 1];
    int i = s;
    for (; i + 1 < e; i += 2) {
        int ed0 = g_csr[i];
        int ed1 = g_csr[i + 1];
        const float4 v0 = __ldcs((const float4*)(efeat + (size_t)ed0 * D_EDGE + c));
        const float4 v1 = __ldcs((const float4*)(efeat + (size_t)ed1 * D_EDGE + c));
        if (PASS) {
            __stcs((float4*)(out_e + (size_t)ed0 * D_EDGE + c), v0);
            __stcs((float4*)(out_e + (size_t)ed1 * D_EDGE + c), v1);
        }
        acc.x += v0.x; acc.y += v0.y; acc.z += v0.z; acc.w += v0.w;
        acc.x += v1.x; acc.y += v1.y; acc.z += v1.z; acc.w += v1.w;
    }
    if (i < e) {
        int ed = g_csr[i];
        const float4 v = __ldcs((const float4*)(efeat + (size_t)ed * D_EDGE + c));
        if (PASS) __stcs((float4*)(out_e + (size_t)ed * D_EDGE + c), v);
        acc.x += v.x; acc.y += v.y; acc.z += v.z; acc.w += v.w;
    }
    __half2 h0 = __floats2half2_rn(acc.x, acc.y);
    __half2 h1 = __floats2half2_rn(acc.z, acc.w);
    *(uint2*)(g_cat + (size_t)n * D_IN + c) = make_uint2(h2_bits(h0), h2_bits(h1));
    const float4 nf = *(const float4*)(nfeat + (size_t)n * D_NODE + c);
    __half2 h2 = __floats2half2_rn(nf.x, nf.y);
    __half2 h3 = __floats2half2_rn(nf.z, nf.w);
    *(uint2*)(g_cat + (size_t)n * D_IN + D_EDGE + c) = make_uint2(h2_bits(h2), h2_bits(h3));
}

// ---------------- weight transpose + fp16 convert ---------------------------
__global__ void transpose_half_kernel(const float* __restrict__ src,
                                      __half* __restrict__ dst, int K, int N) {
    __shared__ float t[32][33];
    int k0 = blockIdx.x * 32, n0 = blockIdx.y * 32;
    int x = threadIdx.x, y0 = threadIdx.y;  // block (32, 8)
#pragma unroll
    for (int d = 0; d < 4; d++) {
        int k = k0 + y0 + d * 8;
        t[y0 + d * 8][x] = src[(size_t)k * N + n0 + x];
    }
    __syncthreads();
#pragma unroll
    for (int d = 0; d < 4; d++) {
        int n = n0 + y0 + d * 8;
        dst[(size_t)n * K + k0 + x] = __float2half_rn(t[x][y0 + d * 8]);
    }
}

// ---------------- fp16 mma.sync GEMM over node range [M0, M_end) ------------
#define HS_STRIDE 40                          // halves per row
#define HS_TILE   (128 * HS_STRIDE * 2)       // bytes per tile: 10240
#define HS_STAGE  (2 * HS_TILE)               // 20480
#define HS_TOTAL  (2 * HS_STAGE)              // 40960

// C output is always fp16 (both g_h and g_y are half now)
template <bool SILU>
__global__ void __launch_bounds__(256) mma_gemm_kernel(
    const __half* __restrict__ A, const __half* __restrict__ Bt,
    const float* __restrict__ bias, __half* __restrict__ C,
    int M0, int M_end, int K)
{
    extern __shared__ char smem[];
    const __half* sh = (const __half*)smem;
    const uint32_t sb = smem_u32_of(smem);
    const int tid = threadIdx.x;
    const int lane = tid & 31;
    const int wid = tid >> 5;
    const int warpRow = wid >> 2;          // 0..1
    const int warpCol = wid & 3;           // 0..3
    const int rowBase = M0 + blockIdx.y * 128;
    const int colBase = blockIdx.x * 128;
    const int NC = K >> 5;

    auto load_chunk = [&](int c, int s) {
        const int kc0 = c << 5;
        const uint32_t stg = (uint32_t)(s * HS_STAGE);
#pragma unroll
        for (int i = 0; i < 2; i++) {
            int idx = tid + (i << 8);          // 0..511
            int r = idx >> 2, seg = idx & 3;
            int gr = rowBase + r;
            if (gr >= M_end) gr = M_end - 1;
            cp16(sb + stg + (uint32_t)(r * (HS_STRIDE * 2) + seg * 16),
                 A + (size_t)gr * K + kc0 + seg * 8);
        }
#pragma unroll
        for (int i = 0; i < 2; i++) {
            int idx = tid + (i << 8);
            int r = idx >> 2, seg = idx & 3;
            cp16(sb + stg + HS_TILE + (uint32_t)(r * (HS_STRIDE * 2) + seg * 16),
                 Bt + (size_t)(colBase + r) * K + kc0 + seg * 8);
        }
        asm volatile("cp.async.commit_group;" ::: "memory");
    };

    float acc[4][4][4];
#pragma unroll
    for (int i = 0; i < 4; i++)
#pragma unroll
        for (int j = 0; j < 4; j++)
#pragma unroll
            for (int r = 0; r < 4; r++) acc[i][j][r] = 0.f;

    load_chunk(0, 0);
    if (NC > 1) load_chunk(1, 1);

    for (int c = 0; c < NC; c++) {
        const int s = c & 1;
        if (c + 1 < NC) asm volatile("cp.async.wait_group 1;" ::: "memory");
        else            asm volatile("cp.async.wait_group 0;" ::: "memory");
        __syncthreads();

        const __half* As = sh + s * (HS_STAGE / 2);
        const __half* Bs = As + (HS_TILE / 2);

#pragma unroll
        for (int ks = 0; ks < 2; ks++) {
            const int kc = (ks << 4) + ((lane & 3) << 1);
            uint32_t af[4][4], bf[4][2];
#pragma unroll
            for (int t = 0; t < 4; t++) {
                int r0 = warpRow * 64 + t * 16 + (lane >> 2);
                af[t][0] = *(const uint32_t*)(As + r0 * HS_STRIDE + kc);
                af[t][1] = *(const uint32_t*)(As + (r0 + 8) * HS_STRIDE + kc);
                af[t][2] = *(const uint32_t*)(As + r0 * HS_STRIDE + kc + 8);
                af[t][3] = *(const uint32_t*)(As + (r0 + 8) * HS_STRIDE + kc + 8);
            }
#pragma unroll
            for (int t = 0; t < 4; t++) {
                int n0 = warpCol * 32 + t * 8 + (lane >> 2);
                bf[t][0] = *(const uint32_t*)(Bs + n0 * HS_STRIDE + kc);
                bf[t][1] = *(const uint32_t*)(Bs + n0 * HS_STRIDE + kc + 8);
            }
#pragma unroll
            for (int mt = 0; mt < 4; mt++)
#pragma unroll
                for (int nt = 0; nt < 4; nt++)
                    mma_fp16(acc[mt][nt], af[mt], bf[nt]);
        }
        __syncthreads();
        if (c + 2 < NC) load_chunk(c + 2, s);
    }

    // epilogue: bias (+ optional silu), write fp16
#pragma unroll
    for (int mt = 0; mt < 4; mt++) {
        int r0 = rowBase + warpRow * 64 + mt * 16 + (lane >> 2);
#pragma unroll
        for (int nt = 0; nt < 4; nt++) {
            int gc = colBase + warpCol * 32 + nt * 8 + ((lane & 3) << 1);
            float bx = bias[gc], by = bias[gc + 1];
#pragma unroll
            for (int h = 0; h < 2; h++) {
                int gr = r0 + h * 8;
                if (gr >= M_end) continue;
                float vx = acc[mt][nt][h * 2 + 0] + bx;
                float vy = acc[mt][nt][h * 2 + 1] + by;
                if (SILU) {
                    vx = vx / (1.f + __expf(-vx));
                    vy = vy / (1.f + __expf(-vy));
                }
                __half2 hv = __floats2half2_rn(vx, vy);
                *(uint32_t*)(C + (size_t)gr * 512 + gc) = h2_bits(hv);
            }
        }
    }
}

// ---------------- LayerNorm + residual (reads fp16 y) -----------------------
__global__ void ln_residual_kernel(const float* __restrict__ nfeat,
                                   const float* __restrict__ gamma,
                                   const float* __restrict__ beta,
                                   float* __restrict__ out, int n0) {
    int n = n0 + blockIdx.x;
    int c = threadIdx.x * 4;
    const uint2 yraw = *(const uint2*)(g_y + (size_t)n * D_OUT + c);
    __half2 yh0, yh1;
    __builtin_memcpy(&yh0, &yraw.x, 4);
    __builtin_memcpy(&yh1, &yraw.y, 4);
    float2 f0 = __half22float2(yh0);
    float2 f1 = __half22float2(yh1);
    float vx = f0.x, vy = f0.y, vz = f1.x, vw = f1.y;

    __shared__ float sm[4];
    __shared__ float sm2[4];
    int lane = threadIdx.x & 31;
    int w = threadIdx.x >> 5;

    float s = vx + vy + vz + vw;
#pragma unroll
    for (int o = 16; o > 0; o >>= 1) s += __shfl_xor_sync(0xffffffffu, s, o);
    if (lane == 0) sm[w] = s;
    __syncthreads();
    float mu = (sm[0] + sm[1] + sm[2] + sm[3]) * (1.f / 512.f);

    float dx = vx - mu, dy = vy - mu, dz = vz - mu, dw = vw - mu;
    float sq = dx * dx + dy * dy + dz * dz + dw * dw;
#pragma unroll
    for (int o = 16; o > 0; o >>= 1) sq += __shfl_xor_sync(0xffffffffu, sq, o);
    if (lane == 0) sm2[w] = sq;
    __syncthreads();
    float var = (sm2[0] + sm2[1] + sm2[2] + sm2[3]) * (1.f / 512.f);
    float inv = rsqrtf(var + LN_EPS);

    const float4 g = *(const float4*)(gamma + c);
    const float4 b = *(const float4*)(beta + c);
    const float4 nf = *(const float4*)(nfeat + (size_t)n * D_NODE + c);
    float4 o4;
    o4.x = dx * inv * g.x + b.x + nf.x;
    o4.y = dy * inv * g.y + b.y + nf.y;
    o4.z = dz * inv * g.z + b.z + nf.z;
    o4.w = dw * inv * g.w + b.w + nf.w;
    *(float4*)(out + (size_t)n * D_OUT + c) = o4;
}

// ---------------- launch ----------------------------------------------------
extern "C" void kernel_launch(void* const* d_in, const int* in_sizes, int n_in,
                              void* d_out, int out_size) {
    const float* efeat   = (const float*)d_in[0];
    const float* nfeat   = (const float*)d_in[1];
    const int*   dst_idx = (const int*)  d_in[2];
    const float* w1      = (const float*)d_in[3];
    const float* b1      = (const float*)d_in[4];
    const float* w2      = (const float*)d_in[5];
    const float* b2      = (const float*)d_in[6];
    const float* gamma   = (const float*)d_in[7];
    const float* beta    = (const float*)d_in[8];

    // device addresses of scratch symbols (NOT the host shadow — see R1)
    __half *cat_p = nullptr, *h_p = nullptr, *y_p = nullptr, *w1t_p = nullptr, *w2t_p = nullptr;
    cudaGetSymbolAddress((void**)&cat_p, g_cat);
    cudaGetSymbolAddress((void**)&h_p,   g_h);
    cudaGetSymbolAddress((void**)&y_p,   g_y);
    cudaGetSymbolAddress((void**)&w1t_p, g_w1t);
    cudaGetSymbolAddress((void**)&w2t_p, g_w2t);

    cudaFuncSetAttribute((const void*)mma_gemm_kernel<true>,
                         cudaFuncAttributeMaxDynamicSharedMemorySize, HS_TOTAL);
    cudaFuncSetAttribute((const void*)mma_gemm_kernel<false>,
                         cudaFuncAttributeMaxDynamicSharedMemorySize, HS_TOTAL);

    float* out = (float*)d_out;
    float* out_nodes;
    const long long full = (long long)N_EDGES * D_EDGE + (long long)N_NODES * D_OUT;
    const bool pass = ((long long)out_size >= full);
    out_nodes = pass ? out + (size_t)N_EDGES * D_EDGE : out;

    // side stream + fork/join events (no device memory alloc)
    cudaStream_t s2 = 0;
    cudaStreamCreateWithFlags(&s2, cudaStreamNonBlocking);
    cudaEvent_t evFork = 0, evW = 0, evA = 0, evB = 0;
    cudaEventCreateWithFlags(&evFork, cudaEventDisableTiming);
    cudaEventCreateWithFlags(&evW, cudaEventDisableTiming);
    cudaEventCreateWithFlags(&evA, cudaEventDisableTiming);
    cudaEventCreateWithFlags(&evB, cudaEventDisableTiming);

    // legal capture fork: s2's first op waits on an origin-stream event
    cudaEventRecord(evFork, 0);
    cudaStreamWaitEvent(s2, evFork, 0);

    // side stream: weight transposes (off the serial prologue)
    {
        dim3 b(32, 8);
        transpose_half_kernel<<<dim3(D_IN / 32, D_HID / 32), b, 0, s2>>>(w1, w1t_p, D_IN, D_HID);
        transpose_half_kernel<<<dim3(D_HID / 32, D_OUT / 32), b, 0, s2>>>(w2, w2t_p, D_HID, D_OUT);
        cudaEventRecord(evW, s2);
    }

    // CSR build (main)
    zero_count_kernel<<<(N_NODES + 255) / 256, 256>>>();
    hist_kernel<<<(N_EDGES + 255) / 256, 256>>>(dst_idx);
    scan1_kernel<<<SCAN_NB, 1024>>>();
    scan2_kernel<<<1, 32>>>();
    scan3_kernel<<<SCAN_NB, 1024>>>();
    fill_kernel<<<(N_EDGES + 255) / 256, 256>>>(dst_idx);

    const int S = NODE_SPLIT;                    // 12544 = 98 x 128
    const int tiles0 = S / 128;                  // 98
    const int tiles1 = (N_NODES - S + 127) / 128;// 98

    // main: agg half0 (full fused passthrough), then fork
    if (pass) agg_concat_kernel<true><<<S, 128>>>(efeat, nfeat, out, 0);
    else      agg_concat_kernel<false><<<S, 128>>>(efeat, nfeat, nullptr, 0);
    cudaEventRecord(evA, 0);

    // main: agg half1 (DRAM-bound) ...
    if (pass) agg_concat_kernel<true><<<N_NODES - S, 128>>>(efeat, nfeat, out, S);
    else      agg_concat_kernel<false><<<N_NODES - S, 128>>>(efeat, nfeat, nullptr, S);

    // ... while s2 runs the (tensor-bound) MLP+LN chain for half0 concurrently
    cudaStreamWaitEvent(s2, evA, 0);
    mma_gemm_kernel<true><<<dim3(4, tiles0), 256, HS_TOTAL, s2>>>(
        cat_p, w1t_p, b1, h_p, 0, S, D_IN);
    mma_gemm_kernel<false><<<dim3(4, tiles0), 256, HS_TOTAL, s2>>>(
        h_p, w2t_p, b2, y_p, 0, S, D_HID);
    ln_residual_kernel<<<S, 128, 0, s2>>>(nfeat, gamma, beta, out_nodes, 0);
    cudaEventRecord(evB, s2);

    // main: needs weights here, before its own GEMM tail
    cudaStreamWaitEvent(0, evW, 0);
    mma_gemm_kernel<true><<<dim3(4, tiles1), 256, HS_TOTAL>>>(
        cat_p, w1t_p, b1, h_p, S, N_NODES, D_IN);
    mma_gemm_kernel<false><<<dim3(4, tiles1), 256, HS_TOTAL>>>(
        h_p, w2t_p, b2, y_p, S, N_NODES, D_HID);
    ln_residual_kernel<<<N_NODES - S, 128>>>(nfeat, gamma, beta, out_nodes, S);

    // join
    cudaStreamWaitEvent(0, evB, 0);
}